// round 6
// baseline (speedup 1.0000x reference)
#include <cuda_runtime.h>
#include <math.h>

#define Bb 4
#define Nn 2047
#define N1 2048
#define Ii 256
#define Oo 128
#define Hh 4
#define SLOPEF 0.2f
#define NBH (Bb * Hh)
#define SEGS 8
#define SEGLEN 256
#define NP1 2049

typedef unsigned long long ull;

// ---------------- scratch (device globals) ----------------
__device__ float g_hph[Bb * Hh * N1 * Oo];      // 16 MB
__device__ float g_ssrc[NBH * N1];
__device__ float g_sdst[NBH * N1];
__device__ float g_Ei[NBH * N1], g_Fi[NBH * N1];
__device__ unsigned char g_runi[NBH * N1];
__device__ float g_part[Bb * 128 * Oo];         // per-tile column sums of hp
__device__ float g_meanhp[NBH * Oo];
__device__ float g_skey[NBH * N1];
__device__ int   g_sidx[NBH * N1];
__device__ float g_wE[NBH * N1], g_wF[NBH * N1];
__device__ float g_SE[(size_t)NBH * NP1 * Oo];
__device__ float g_PF[(size_t)NBH * NP1 * Oo];
__device__ float g_sSE[NBH * NP1], g_sPF[NBH * NP1];
__device__ float g_offE[NBH * SEGS * Oo], g_offF[NBH * SEGS * Oo];
__device__ float g_soffE[NBH * SEGS], g_soffF[NBH * SEGS];
__device__ int g_mask_is_int = 1;               // static init; kdetect only lowers to 0

// ---------------- mask dtype detection ----------------
__global__ void kdetect_mask(const unsigned* __restrict__ m) {
    int idx = blockIdx.x * 256 + threadIdx.x;   // 2048 words = 8192 bytes, safe either way
    if (m[idx] > 1u) g_mask_is_int = 0;
}
__device__ __forceinline__ bool mask_at(const void* m, int idx) {
    if (g_mask_is_int) return ((const int*)m)[idx] != 0;
    return ((const unsigned char*)m)[idx] != 0;
}

__device__ __forceinline__ float fast_tanh(float x) {
    float cx = fminf(fmaxf(x, -15.f), 15.f);
    float e = __expf(2.f * cx);
    return __fdividef(e - 1.f, e + 1.f);
}

__device__ __forceinline__ ull packf2(float v) {
    ull r;
    asm("mov.b64 %0, {%1, %1};" : "=l"(r) : "f"(v));
    return r;
}
__device__ __forceinline__ void fma2(ull& d, ull a, ull b) {
    asm("fma.rn.f32x2 %0, %1, %2, %0;" : "+l"(d) : "l"(a), "l"(b));
}
__device__ __forceinline__ void unpackf2(ull v, float& lo, float& hi) {
    asm("mov.b64 {%0, %1}, %2;" : "=f"(lo), "=f"(hi) : "l"(v));
}

// ---------------- K12: fused self_linear + head projection + scores + hp tile sums --------
// Block: 256 threads, 32-row tile. Phase A: hp tile (K=256). Phase B: 4 heads (K=128).
// Thread map: tr = t>>4 -> rows {tr, tr+16}; tc = t&15 -> col pairs {2tc+32c}, c<4.
__global__ __launch_bounds__(256) void k12_fused(const float* __restrict__ x,
                                                 const float* __restrict__ prior,
                                                 const float* __restrict__ Wlin,
                                                 const float* __restrict__ whead,
                                                 const float* __restrict__ asrc,
                                                 const float* __restrict__ adst) {
    __shared__ float xs[32][33];
    __shared__ float ws2[32][130];   // phase A: W^T chunk [k][p]; phase B: w_head chunk [o][p]
    __shared__ float hpt[32][130];   // hp tile (rows x 128 cols, pad 2)

    const int ib = blockIdx.x;
    const int nb = ib * 32;
    const int b = blockIdx.y;
    const int t = threadIdx.x;
    const int tr = t >> 4;
    const int tc = t & 15;

    // ---- Phase A: hp tile ----
    ull acc[2][4];
#pragma unroll
    for (int ar = 0; ar < 2; ++ar)
#pragma unroll
        for (int c = 0; c < 4; ++c) acc[ar][c] = 0ull;

    for (int kb = 0; kb < Ii; kb += 32) {
        __syncthreads();
#pragma unroll
        for (int it = 0; it < 4; ++it) {
            int idx = t + 256 * it;
            int r = idx >> 5, k = idx & 31;
            int gn = nb + r;
            xs[r][k] = (gn < Nn) ? x[(b * Nn + gn) * Ii + kb + k] : 0.f;
        }
#pragma unroll
        for (int it = 0; it < 16; ++it) {
            int idx = t + 256 * it;
            int p = idx >> 5, k = idx & 31;
            ws2[k][p] = Wlin[p * Ii + kb + k];   // transposed store
        }
        __syncthreads();
#pragma unroll
        for (int k = 0; k < 32; ++k) {
            ull pp0 = packf2(xs[tr][k]);
            ull pp1 = packf2(xs[tr + 16][k]);
#pragma unroll
            for (int c = 0; c < 4; ++c) {
                ull wv = *(const ull*)&ws2[k][2 * tc + 32 * c];
                fma2(acc[0][c], pp0, wv);
                fma2(acc[1][c], pp1, wv);
            }
        }
    }
    // epilogue A: prior row substitution, store to smem
#pragma unroll
    for (int ar = 0; ar < 2; ++ar) {
        int r = tr + 16 * ar;
        int gn = nb + r;
        bool isprior = (gn == Nn);
#pragma unroll
        for (int c = 0; c < 4; ++c) {
            int col = 2 * tc + 32 * c;
            float lo, hi;
            unpackf2(acc[ar][c], lo, hi);
            if (isprior) { lo = prior[b * Oo + col]; hi = prior[b * Oo + col + 1]; }
            hpt[r][col] = lo;
            hpt[r][col + 1] = hi;
        }
    }
    __syncthreads();
    // per-tile column sums (replaces the old k2b global pass)
    {
        int col = t & 127;
        int half = t >> 7;
        float s = 0.f;
#pragma unroll
        for (int r = half * 16; r < half * 16 + 16; ++r) s += hpt[r][col];
        g_part[((b * 64 + ib) * 2 + half) * Oo + col] = s;
    }

    // ---- Phase B: per-head projection + scores ----
    for (int h = 0; h < Hh; ++h) {
        ull a2[2][4];
#pragma unroll
        for (int ar = 0; ar < 2; ++ar)
#pragma unroll
            for (int c = 0; c < 4; ++c) a2[ar][c] = 0ull;

        for (int kb = 0; kb < Oo; kb += 32) {
            __syncthreads();
#pragma unroll
            for (int it = 0; it < 16; ++it) {
                int idx = t + 256 * it;
                int o = idx >> 7, p = idx & 127;
                ws2[o][p] = whead[(size_t)(h * Oo + kb + o) * Oo + p];
            }
            __syncthreads();
#pragma unroll
            for (int k = 0; k < 32; ++k) {
                ull pp0 = packf2(hpt[tr][kb + k]);
                ull pp1 = packf2(hpt[tr + 16][kb + k]);
#pragma unroll
                for (int c = 0; c < 4; ++c) {
                    ull wv = *(const ull*)&ws2[k][2 * tc + 32 * c];
                    fma2(a2[0][c], pp0, wv);
                    fma2(a2[1][c], pp1, wv);
                }
            }
        }
        // epilogue B: write hph, fused tanh-dot scores
        const int bh = b * Hh + h;
#pragma unroll
        for (int ar = 0; ar < 2; ++ar) {
            int r = tr + 16 * ar;
            int gn = nb + r;
            float ps = 0.f, pd = 0.f;
#pragma unroll
            for (int c = 0; c < 4; ++c) {
                int col = 2 * tc + 32 * c;
                float lo, hi;
                unpackf2(a2[ar][c], lo, hi);
                *(float2*)&g_hph[((size_t)bh * N1 + gn) * Oo + col] = make_float2(lo, hi);
                float t0 = fast_tanh(lo);
                float t1 = fast_tanh(hi);
                ps = fmaf(t0, asrc[h * Oo + col], fmaf(t1, asrc[h * Oo + col + 1], ps));
                pd = fmaf(t0, adst[h * Oo + col], fmaf(t1, adst[h * Oo + col + 1], pd));
            }
#pragma unroll
            for (int off = 8; off; off >>= 1) {
                ps += __shfl_xor_sync(0xffffffffu, ps, off);
                pd += __shfl_xor_sync(0xffffffffu, pd, off);
            }
            if (tc == 0) {
                g_ssrc[bh * N1 + gn] = ps;
                g_sdst[bh * N1 + gn] = pd;
            }
        }
    }
}

// ---------------- K2c: meanhp[b,h] = (reduce g_part -> mhp0[b]) @ w_head[h] ----------------
__global__ __launch_bounds__(128) void k2c_meanhp(const float* __restrict__ whead) {
    __shared__ float m0[Oo];
    const int h = blockIdx.x;
    const int b = blockIdx.y;
    const int t = threadIdx.x;
    float s = 0.f;
#pragma unroll 4
    for (int p = 0; p < 128; ++p) s += g_part[(b * 128 + p) * Oo + t];
    m0[t] = s * (1.f / (float)N1);
    __syncthreads();
    float acc = 0.f;
#pragma unroll 8
    for (int o = 0; o < Oo; ++o) acc = fmaf(m0[o], whead[(h * Oo + o) * Oo + t], acc);
    g_meanhp[(b * Hh + h) * Oo + t] = acc;
}

// ---------------- KSortM: fused factors (Mdst, Ei/Fi/Ej/Fj/runi) + bitonic sort ------------
__global__ __launch_bounds__(1024) void ksortm(const void* __restrict__ xmask) {
    __shared__ float key[N1];
    __shared__ int idx[N1];
    __shared__ float Ejs[N1], Fjs[N1];
    __shared__ float red32[32];
    const int bh = blockIdx.x;
    const int b = bh / Hh;
    const int t = threadIdx.x;

    // Mdst = max over unmasked j of s_dst
    float mx = -INFINITY;
#pragma unroll
    for (int n = t; n < N1; n += 1024)
        if (!mask_at(xmask, b * N1 + n)) mx = fmaxf(mx, g_sdst[bh * N1 + n]);
#pragma unroll
    for (int off = 16; off; off >>= 1) mx = fmaxf(mx, __shfl_xor_sync(0xffffffffu, mx, off));
    if ((t & 31) == 0) red32[t >> 5] = mx;
    __syncthreads();
    if (t == 0) {
        float m = red32[0];
#pragma unroll
        for (int i = 1; i < 32; ++i) m = fmaxf(m, red32[i]);
        red32[0] = m;
    }
    __syncthreads();
    const float Mdst = red32[0];
    const bool nou = (Mdst == -INFINITY);

    // factors
#pragma unroll
    for (int n = t; n < N1; n += 1024) {
        int gidx = bh * N1 + n;
        float sd = g_sdst[gidx];
        float si = g_ssrc[gidx];
        bool dead = nou || mask_at(xmask, b * N1 + n);
        Ejs[n] = dead ? 0.f : expf(sd - Mdst);
        Fjs[n] = dead ? 0.f : expf(SLOPEF * (sd - Mdst));
        float xm = si + Mdst;
        float m = (xm >= 0.f) ? xm : SLOPEF * xm;
        g_Ei[gidx] = dead ? 0.f : expf(xm - m);
        g_Fi[gidx] = dead ? 0.f : expf(SLOPEF * xm - m);
        g_runi[gidx] = dead ? 1 : 0;
        key[n] = sd;
        idx[n] = n;
    }
    __syncthreads();

    // bitonic sort ascending by key
    for (int k = 2; k <= N1; k <<= 1) {
        for (int j = k >> 1; j > 0; j >>= 1) {
#pragma unroll 2
            for (int i = t; i < N1; i += 1024) {
                int ixj = i ^ j;
                if (ixj > i) {
                    bool up = ((i & k) == 0);
                    float ki = key[i], kj = key[ixj];
                    if (up ? (ki > kj) : (ki < kj)) {
                        key[i] = kj; key[ixj] = ki;
                        int tmp = idx[i]; idx[i] = idx[ixj]; idx[ixj] = tmp;
                    }
                }
            }
            __syncthreads();
        }
    }
#pragma unroll
    for (int r = t; r < N1; r += 1024) {
        int j = idx[r];
        g_skey[bh * N1 + r] = key[r];
        g_sidx[bh * N1 + r] = j;
        g_wE[bh * N1 + r] = Ejs[j];
        g_wF[bh * N1 + r] = Fjs[j];
    }
}

// ---------------- KScan: segmented scans of wE*hph (suffix) & wF*hph (prefix) ----------------
__global__ __launch_bounds__(256) void kscan() {
    __shared__ float wE[SEGLEN], wF[SEGLEN];
    __shared__ int sidx[SEGLEN];
    const int s = blockIdx.x;
    const int bh = blockIdx.y;
    const int t = threadIdx.x;
    const int col = t & 127;
    const int job = t >> 7;

    {
        int r = s * SEGLEN + t;
        if (t < SEGLEN) {
            wE[t] = g_wE[bh * N1 + r];
            wF[t] = g_wF[bh * N1 + r];
            sidx[t] = g_sidx[bh * N1 + r];
        }
    }
    __syncthreads();

    const float* hph = g_hph + (size_t)bh * N1 * Oo;
    const size_t outbase = ((size_t)bh * NP1 + s * SEGLEN) * Oo;

    if (job == 0) {
        float acc = 0.f, sacc = 0.f;
#pragma unroll 4
        for (int r = 0; r < SEGLEN; ++r) {
            float v = hph[(size_t)sidx[r] * Oo + col];
            acc = fmaf(wF[r], v, acc);
            g_PF[outbase + (size_t)(r + 1) * Oo + col] = acc;
            if (col == 0) {
                sacc += wF[r];
                g_sPF[bh * NP1 + s * SEGLEN + r + 1] = sacc;
            }
        }
    } else {
        float acc = 0.f, sacc = 0.f;
#pragma unroll 4
        for (int r = SEGLEN - 1; r >= 0; --r) {
            float v = hph[(size_t)sidx[r] * Oo + col];
            acc = fmaf(wE[r], v, acc);
            g_SE[outbase + (size_t)r * Oo + col] = acc;
            if (col == 0) {
                sacc += wE[r];
                g_sSE[bh * NP1 + s * SEGLEN + r] = sacc;
            }
        }
    }
}

// ---------------- KOff: per-segment offsets ----------------
__global__ __launch_bounds__(128) void koff() {
    const int bh = blockIdx.x;
    const int col = threadIdx.x;
    float acc = 0.f;
    for (int s = SEGS - 1; s >= 0; --s) {
        g_offE[(bh * SEGS + s) * Oo + col] = acc;
        acc += g_SE[((size_t)bh * NP1 + s * SEGLEN) * Oo + col];
    }
    float accF = 0.f;
    for (int s = 0; s < SEGS; ++s) {
        g_offF[(bh * SEGS + s) * Oo + col] = accF;
        accF += g_PF[((size_t)bh * NP1 + s * SEGLEN + SEGLEN) * Oo + col];
    }
    if (col == 0) {
        float a = 0.f;
        for (int s = SEGS - 1; s >= 0; --s) {
            g_soffE[bh * SEGS + s] = a;
            a += g_sSE[bh * NP1 + s * SEGLEN];
        }
        float aF = 0.f;
        for (int s = 0; s < SEGS; ++s) {
            g_soffF[bh * SEGS + s] = aF;
            aF += g_sPF[bh * NP1 + s * SEGLEN + SEGLEN];
        }
    }
}

// ---------------- KOut: threshold lookup + combine + head-mean + bias ----------------
__global__ __launch_bounds__(256) void kout(const float* __restrict__ bias,
                                            float* __restrict__ out) {
    __shared__ float keys[N1];
    __shared__ float mhs[Oo];
    __shared__ int tis[32];
    __shared__ float Eis[32], Fis[32], invl[32];
    __shared__ unsigned char runi[32];

    const int ib = blockIdx.x;
    const int b = blockIdx.y;
    const int t = threadIdx.x;
    const int col = t & 127;
    const int rh = t >> 7;

    float sum[16];
#pragma unroll
    for (int rr = 0; rr < 16; ++rr) sum[rr] = 0.f;

    for (int h = 0; h < Hh; ++h) {
        const int bh = b * Hh + h;
        __syncthreads();
        for (int i = t; i < N1; i += 256) keys[i] = g_skey[bh * N1 + i];
        if (t < Oo) mhs[t] = g_meanhp[bh * Oo + t];
        __syncthreads();

        if (t < 32) {
            int gi = ib * 32 + t;
            int idx = bh * N1 + gi;
            float si = g_ssrc[idx];
            float target = -si;
            int lo = 0, hi = N1;
            while (lo < hi) {
                int mid = (lo + hi) >> 1;
                if (keys[mid] >= target) hi = mid; else lo = mid + 1;
            }
            int ti = lo;
            float Ei = g_Ei[idx], Fi = g_Fi[idx];
            float sse = (ti == N1) ? 0.f : g_sSE[bh * NP1 + ti] + g_soffE[bh * SEGS + (ti >> 8)];
            float spf = (ti == 0) ? 0.f : g_sPF[bh * NP1 + ti] + g_soffF[bh * SEGS + ((ti - 1) >> 8)];
            float li = Ei * sse + Fi * spf;
            tis[t] = ti;
            Eis[t] = Ei;
            Fis[t] = Fi;
            invl[t] = 1.f / li;
            runi[t] = g_runi[idx];
        }
        __syncthreads();

#pragma unroll 4
        for (int rr = 0; rr < 16; ++rr) {
            int r = rh + 2 * rr;
            if (runi[r]) { sum[rr] += mhs[col]; continue; }
            int ti = tis[r];
            float se = (ti == N1) ? 0.f
                : g_SE[((size_t)bh * NP1 + ti) * Oo + col] + g_offE[(bh * SEGS + (ti >> 8)) * Oo + col];
            float pf = (ti == 0) ? 0.f
                : g_PF[((size_t)bh * NP1 + ti) * Oo + col] + g_offF[(bh * SEGS + ((ti - 1) >> 8)) * Oo + col];
            sum[rr] += (Eis[r] * se + Fis[r] * pf) * invl[r];
        }
    }

    float* outp = out + ((size_t)b * N1 + ib * 32) * Oo;
#pragma unroll
    for (int rr = 0; rr < 16; ++rr) {
        int r = rh + 2 * rr;
        outp[r * Oo + col] = 0.25f * sum[rr] + bias[col];
    }
}

// ---------------- launch ----------------
extern "C" void kernel_launch(void* const* d_in, const int* in_sizes, int n_in,
                              void* d_out, int out_size) {
    const float* x = (const float*)d_in[0];
    const float* prior = (const float*)d_in[1];
    const void* xmask = d_in[2];
    const float* Wlin = (const float*)d_in[3];
    const float* whead = (const float*)d_in[4];
    const float* asrc = (const float*)d_in[5];
    const float* adst = (const float*)d_in[6];
    const float* bias = (const float*)d_in[7];
    float* out = (float*)d_out;

    kdetect_mask<<<8, 256>>>((const unsigned*)xmask);
    k12_fused<<<dim3(64, Bb), 256>>>(x, prior, Wlin, whead, asrc, adst);
    k2c_meanhp<<<dim3(Hh, Bb), 128>>>(whead);
    ksortm<<<NBH, 1024>>>(xmask);
    kscan<<<dim3(SEGS, NBH), 256>>>();
    koff<<<NBH, 128>>>();
    kout<<<dim3(64, Bb), 256>>>(bias, out);
}

// round 8
// speedup vs baseline: 1.1645x; 1.1645x over previous
#include <cuda_runtime.h>
#include <math.h>

#define Bb 4
#define Nn 2047
#define N1 2048
#define Ii 256
#define Oo 128
#define Hh 4
#define SLOPEF 0.2f
#define NBH (Bb * Hh)
#define SEGS 8
#define SEGLEN 256
#define NP1 2049

typedef unsigned long long ull;

// ---------------- scratch (device globals) ----------------
__device__ float g_hph[Bb * Hh * N1 * Oo];      // 16 MB
__device__ float g_ssrc[NBH * N1];
__device__ float g_sdst[NBH * N1];
__device__ float g_Ei[NBH * N1], g_Fi[NBH * N1];
__device__ unsigned char g_runi[NBH * N1];
__device__ float g_part[Bb * 128 * Oo];         // per-tile column sums of hp
__device__ float g_meanhp[NBH * Oo];
__device__ float g_skey[NBH * N1];
__device__ int   g_sidx[NBH * N1];
__device__ float g_wE[NBH * N1], g_wF[NBH * N1];
__device__ float g_SE[(size_t)NBH * NP1 * Oo];
__device__ float g_PF[(size_t)NBH * NP1 * Oo];
__device__ float g_sSE[NBH * NP1], g_sPF[NBH * NP1];
__device__ float g_offE[NBH * SEGS * Oo], g_offF[NBH * SEGS * Oo];
__device__ float g_soffE[NBH * SEGS], g_soffF[NBH * SEGS];
__device__ int   g_ti[NBH * N1];
__device__ float g_invl[NBH * N1];
__device__ int g_mask_is_int = 1;               // static init; kdetect only lowers to 0

// ---------------- mask dtype detection ----------------
__global__ void kdetect_mask(const unsigned* __restrict__ m) {
    int idx = blockIdx.x * 256 + threadIdx.x;   // 2048 words = 8192 bytes, safe either way
    if (m[idx] > 1u) g_mask_is_int = 0;
}
__device__ __forceinline__ bool mask_at(const void* m, int idx) {
    if (g_mask_is_int) return ((const int*)m)[idx] != 0;
    return ((const unsigned char*)m)[idx] != 0;
}

__device__ __forceinline__ float fast_tanh(float x) {
    float cx = fminf(fmaxf(x, -15.f), 15.f);
    float e = __expf(2.f * cx);
    return __fdividef(e - 1.f, e + 1.f);
}

__device__ __forceinline__ ull packf2(float v) {
    ull r;
    asm("mov.b64 %0, {%1, %1};" : "=l"(r) : "f"(v));
    return r;
}
__device__ __forceinline__ void fma2(ull& d, ull a, ull b) {
    asm("fma.rn.f32x2 %0, %1, %2, %0;" : "+l"(d) : "l"(a), "l"(b));
}
__device__ __forceinline__ void unpackf2(ull v, float& lo, float& hi) {
    asm("mov.b64 {%0, %1}, %2;" : "=f"(lo), "=f"(hi) : "l"(v));
}
// monotone float -> uint32 mapping for sorting
__device__ __forceinline__ unsigned f2sort(float f) {
    unsigned u = __float_as_uint(f);
    return u ^ ((unsigned)((int)u >> 31) | 0x80000000u);
}

// ---------------- K12: fused self_linear + head projection + scores + hp tile sums --------
__global__ __launch_bounds__(256) void k12_fused(const float* __restrict__ x,
                                                 const float* __restrict__ prior,
                                                 const float* __restrict__ Wlin,
                                                 const float* __restrict__ whead,
                                                 const float* __restrict__ asrc,
                                                 const float* __restrict__ adst) {
    __shared__ float xs[32][33];
    __shared__ float ws2[32][130];
    __shared__ float hpt[32][130];

    const int ib = blockIdx.x;
    const int nb = ib * 32;
    const int b = blockIdx.y;
    const int t = threadIdx.x;
    const int tr = t >> 4;
    const int tc = t & 15;

    // ---- Phase A: hp tile ----
    ull acc[2][4];
#pragma unroll
    for (int ar = 0; ar < 2; ++ar)
#pragma unroll
        for (int c = 0; c < 4; ++c) acc[ar][c] = 0ull;

    for (int kb = 0; kb < Ii; kb += 32) {
        __syncthreads();
#pragma unroll
        for (int it = 0; it < 4; ++it) {
            int idx = t + 256 * it;
            int r = idx >> 5, k = idx & 31;
            int gn = nb + r;
            xs[r][k] = (gn < Nn) ? x[(b * Nn + gn) * Ii + kb + k] : 0.f;
        }
#pragma unroll
        for (int it = 0; it < 16; ++it) {
            int idx = t + 256 * it;
            int p = idx >> 5, k = idx & 31;
            ws2[k][p] = Wlin[p * Ii + kb + k];
        }
        __syncthreads();
#pragma unroll
        for (int k = 0; k < 32; ++k) {
            ull pp0 = packf2(xs[tr][k]);
            ull pp1 = packf2(xs[tr + 16][k]);
#pragma unroll
            for (int c = 0; c < 4; ++c) {
                ull wv = *(const ull*)&ws2[k][2 * tc + 32 * c];
                fma2(acc[0][c], pp0, wv);
                fma2(acc[1][c], pp1, wv);
            }
        }
    }
#pragma unroll
    for (int ar = 0; ar < 2; ++ar) {
        int r = tr + 16 * ar;
        int gn = nb + r;
        bool isprior = (gn == Nn);
#pragma unroll
        for (int c = 0; c < 4; ++c) {
            int col = 2 * tc + 32 * c;
            float lo, hi;
            unpackf2(acc[ar][c], lo, hi);
            if (isprior) { lo = prior[b * Oo + col]; hi = prior[b * Oo + col + 1]; }
            hpt[r][col] = lo;
            hpt[r][col + 1] = hi;
        }
    }
    __syncthreads();
    // per-tile column sums (for meanhp)
    {
        int col = t & 127;
        int half = t >> 7;
        float s = 0.f;
#pragma unroll
        for (int r = half * 16; r < half * 16 + 16; ++r) s += hpt[r][col];
        g_part[((b * 64 + ib) * 2 + half) * Oo + col] = s;
    }

    // ---- Phase B: per-head projection + scores ----
    for (int h = 0; h < Hh; ++h) {
        ull a2[2][4];
#pragma unroll
        for (int ar = 0; ar < 2; ++ar)
#pragma unroll
            for (int c = 0; c < 4; ++c) a2[ar][c] = 0ull;

        for (int kb = 0; kb < Oo; kb += 32) {
            __syncthreads();
#pragma unroll
            for (int it = 0; it < 16; ++it) {
                int idx = t + 256 * it;
                int o = idx >> 7, p = idx & 127;
                ws2[o][p] = whead[(size_t)(h * Oo + kb + o) * Oo + p];
            }
            __syncthreads();
#pragma unroll
            for (int k = 0; k < 32; ++k) {
                ull pp0 = packf2(hpt[tr][kb + k]);
                ull pp1 = packf2(hpt[tr + 16][kb + k]);
#pragma unroll
                for (int c = 0; c < 4; ++c) {
                    ull wv = *(const ull*)&ws2[k][2 * tc + 32 * c];
                    fma2(a2[0][c], pp0, wv);
                    fma2(a2[1][c], pp1, wv);
                }
            }
        }
        const int bh = b * Hh + h;
#pragma unroll
        for (int ar = 0; ar < 2; ++ar) {
            int r = tr + 16 * ar;
            int gn = nb + r;
            float ps = 0.f, pd = 0.f;
#pragma unroll
            for (int c = 0; c < 4; ++c) {
                int col = 2 * tc + 32 * c;
                float lo, hi;
                unpackf2(a2[ar][c], lo, hi);
                *(float2*)&g_hph[((size_t)bh * N1 + gn) * Oo + col] = make_float2(lo, hi);
                float t0 = fast_tanh(lo);
                float t1 = fast_tanh(hi);
                ps = fmaf(t0, asrc[h * Oo + col], fmaf(t1, asrc[h * Oo + col + 1], ps));
                pd = fmaf(t0, adst[h * Oo + col], fmaf(t1, adst[h * Oo + col + 1], pd));
            }
#pragma unroll
            for (int off = 8; off; off >>= 1) {
                ps += __shfl_xor_sync(0xffffffffu, ps, off);
                pd += __shfl_xor_sync(0xffffffffu, pd, off);
            }
            if (tc == 0) {
                g_ssrc[bh * N1 + gn] = ps;
                g_sdst[bh * N1 + gn] = pd;
            }
        }
    }
}

// ---------------- K2c: meanhp[b,h] = (reduce g_part -> mhp0[b]) @ w_head[h] ----------------
__global__ __launch_bounds__(128) void k2c_meanhp(const float* __restrict__ whead) {
    __shared__ float m0[Oo];
    const int h = blockIdx.x;
    const int b = blockIdx.y;
    const int t = threadIdx.x;
    float s = 0.f;
#pragma unroll 4
    for (int p = 0; p < 128; ++p) s += g_part[(b * 128 + p) * Oo + t];
    m0[t] = s * (1.f / (float)N1);
    __syncthreads();
    float acc = 0.f;
#pragma unroll 8
    for (int o = 0; o < Oo; ++o) acc = fmaf(m0[o], whead[(h * Oo + o) * Oo + t], acc);
    g_meanhp[(b * Hh + h) * Oo + t] = acc;
}

// ---------------- KSortM: factors + composite-key bitonic sort ----------------
__global__ __launch_bounds__(1024) void ksortm(const void* __restrict__ xmask) {
    __shared__ ull comp[N1];        // 16 KB composite (sortable key << 16 | idx)
    __shared__ float sds[N1];       // 8 KB raw s_dst
    __shared__ float Ejs[N1], Fjs[N1];
    __shared__ float red32[32];
    const int bh = blockIdx.x;
    const int b = bh / Hh;
    const int t = threadIdx.x;

    // load s_dst, Mdst reduction
    float mx = -INFINITY;
#pragma unroll
    for (int n = t; n < N1; n += 1024) {
        float sd = g_sdst[bh * N1 + n];
        sds[n] = sd;
        if (!mask_at(xmask, b * N1 + n)) mx = fmaxf(mx, sd);
    }
#pragma unroll
    for (int off = 16; off; off >>= 1) mx = fmaxf(mx, __shfl_xor_sync(0xffffffffu, mx, off));
    if ((t & 31) == 0) red32[t >> 5] = mx;
    __syncthreads();
    if (t == 0) {
        float m = red32[0];
#pragma unroll
        for (int i = 1; i < 32; ++i) m = fmaxf(m, red32[i]);
        red32[0] = m;
    }
    __syncthreads();
    const float Mdst = red32[0];
    const bool nou = (Mdst == -INFINITY);

    // factors + composites
#pragma unroll
    for (int n = t; n < N1; n += 1024) {
        int gidx = bh * N1 + n;
        float sd = sds[n];
        float si = g_ssrc[gidx];
        bool dead = nou || mask_at(xmask, b * N1 + n);
        Ejs[n] = dead ? 0.f : expf(sd - Mdst);
        Fjs[n] = dead ? 0.f : expf(SLOPEF * (sd - Mdst));
        float xm = si + Mdst;
        float m = (xm >= 0.f) ? xm : SLOPEF * xm;
        g_Ei[gidx] = dead ? 0.f : expf(xm - m);
        g_Fi[gidx] = dead ? 0.f : expf(SLOPEF * xm - m);
        g_runi[gidx] = dead ? 1 : 0;
        comp[n] = ((ull)f2sort(sd) << 16) | (unsigned)n;
    }
    __syncthreads();

    // bitonic sort ascending on composites.
    // Steps with j<32 have warp-local partners -> __syncwarp inside the merge.
    // A full __syncthreads at the END of each k-merge makes small-j writes
    // visible before the next merge's cross-warp reads (this was R7's race).
    for (int k = 2; k <= N1; k <<= 1) {
        for (int j = k >> 1; j > 0; j >>= 1) {
#pragma unroll 2
            for (int i = t; i < N1; i += 1024) {
                int ixj = i ^ j;
                if (ixj > i) {
                    bool up = ((i & k) == 0);
                    ull ci = comp[i], cj = comp[ixj];
                    if (up ? (ci > cj) : (ci < cj)) {
                        comp[i] = cj;
                        comp[ixj] = ci;
                    }
                }
            }
            if (j >= 32) __syncthreads(); else __syncwarp();
        }
        __syncthreads();   // merge boundary: next k starts with cross-warp reads
    }
#pragma unroll
    for (int r = t; r < N1; r += 1024) {
        int j = (int)(comp[r] & 0xFFFFu);
        g_skey[bh * N1 + r] = sds[j];
        g_sidx[bh * N1 + r] = j;
        g_wE[bh * N1 + r] = Ejs[j];
        g_wF[bh * N1 + r] = Fjs[j];
    }
}

// ---------------- KScan: segmented scans of wE*hph (suffix) & wF*hph (prefix) ----------------
__global__ __launch_bounds__(256) void kscan() {
    __shared__ float wE[SEGLEN], wF[SEGLEN];
    __shared__ int sidx[SEGLEN];
    const int s = blockIdx.x;
    const int bh = blockIdx.y;
    const int t = threadIdx.x;
    const int col = t & 127;
    const int job = t >> 7;

    {
        int r = s * SEGLEN + t;
        if (t < SEGLEN) {
            wE[t] = g_wE[bh * N1 + r];
            wF[t] = g_wF[bh * N1 + r];
            sidx[t] = g_sidx[bh * N1 + r];
        }
    }
    __syncthreads();

    const float* hph = g_hph + (size_t)bh * N1 * Oo;
    const size_t outbase = ((size_t)bh * NP1 + s * SEGLEN) * Oo;

    if (job == 0) {
        float acc = 0.f, sacc = 0.f;
#pragma unroll 4
        for (int r = 0; r < SEGLEN; ++r) {
            float v = hph[(size_t)sidx[r] * Oo + col];
            acc = fmaf(wF[r], v, acc);
            g_PF[outbase + (size_t)(r + 1) * Oo + col] = acc;
            if (col == 0) {
                sacc += wF[r];
                g_sPF[bh * NP1 + s * SEGLEN + r + 1] = sacc;
            }
        }
    } else {
        float acc = 0.f, sacc = 0.f;
#pragma unroll 4
        for (int r = SEGLEN - 1; r >= 0; --r) {
            float v = hph[(size_t)sidx[r] * Oo + col];
            acc = fmaf(wE[r], v, acc);
            g_SE[outbase + (size_t)r * Oo + col] = acc;
            if (col == 0) {
                sacc += wE[r];
                g_sSE[bh * NP1 + s * SEGLEN + r] = sacc;
            }
        }
    }
}

// ---------------- KOff: per-segment offsets ----------------
__global__ __launch_bounds__(128) void koff() {
    const int bh = blockIdx.x;
    const int col = threadIdx.x;
    float acc = 0.f;
    for (int s = SEGS - 1; s >= 0; --s) {
        g_offE[(bh * SEGS + s) * Oo + col] = acc;
        acc += g_SE[((size_t)bh * NP1 + s * SEGLEN) * Oo + col];
    }
    float accF = 0.f;
    for (int s = 0; s < SEGS; ++s) {
        g_offF[(bh * SEGS + s) * Oo + col] = accF;
        accF += g_PF[((size_t)bh * NP1 + s * SEGLEN + SEGLEN) * Oo + col];
    }
    if (col == 0) {
        float a = 0.f;
        for (int s = SEGS - 1; s >= 0; --s) {
            g_soffE[bh * SEGS + s] = a;
            a += g_sSE[bh * NP1 + s * SEGLEN];
        }
        float aF = 0.f;
        for (int s = 0; s < SEGS; ++s) {
            g_soffF[bh * SEGS + s] = aF;
            aF += g_sPF[bh * NP1 + s * SEGLEN + SEGLEN];
        }
    }
}

// ---------------- KTi: per-row threshold (binary search) + 1/l ----------------
__global__ __launch_bounds__(1024) void kti() {
    __shared__ float keys[N1];
    const int bh = blockIdx.x;
    const int t = threadIdx.x;
    for (int i = t; i < N1; i += 1024) keys[i] = g_skey[bh * N1 + i];
    __syncthreads();
#pragma unroll
    for (int i = t; i < N1; i += 1024) {
        int idx = bh * N1 + i;
        float target = -g_ssrc[idx];
        int lo = 0, hi = N1;
#pragma unroll
        for (int it = 0; it < 11; ++it) {
            int mid = (lo + hi) >> 1;
            if (keys[mid] >= target) hi = mid; else lo = mid + 1;
        }
        int ti = lo;
        float Ei = g_Ei[idx], Fi = g_Fi[idx];
        float sse = (ti == N1) ? 0.f : g_sSE[bh * NP1 + ti] + g_soffE[bh * SEGS + (ti >> 8)];
        float spf = (ti == 0) ? 0.f : g_sPF[bh * NP1 + ti] + g_soffF[bh * SEGS + ((ti - 1) >> 8)];
        float li = Ei * sse + Fi * spf;
        g_ti[idx] = ti;
        g_invl[idx] = 1.f / li;
    }
}

// ---------------- KOut: gather + combine + head-mean + bias ----------------
__global__ __launch_bounds__(256) void kout(const float* __restrict__ bias,
                                            float* __restrict__ out) {
    __shared__ float mhs[Oo];
    __shared__ int tis[32];
    __shared__ float Eis[32], Fis[32], invl[32];
    __shared__ unsigned char runi[32];

    const int ib = blockIdx.x;
    const int b = blockIdx.y;
    const int t = threadIdx.x;
    const int col = t & 127;
    const int rh = t >> 7;

    float sum[16];
#pragma unroll
    for (int rr = 0; rr < 16; ++rr) sum[rr] = 0.f;

    for (int h = 0; h < Hh; ++h) {
        const int bh = b * Hh + h;
        __syncthreads();
        if (t < 32) {
            int idx = bh * N1 + ib * 32 + t;
            tis[t] = g_ti[idx];
            Eis[t] = g_Ei[idx];
            Fis[t] = g_Fi[idx];
            invl[t] = g_invl[idx];
            runi[t] = g_runi[idx];
        }
        if (t < Oo) mhs[t] = g_meanhp[bh * Oo + t];
        __syncthreads();

#pragma unroll 4
        for (int rr = 0; rr < 16; ++rr) {
            int r = rh + 2 * rr;
            if (runi[r]) { sum[rr] += mhs[col]; continue; }
            int ti = tis[r];
            float se = (ti == N1) ? 0.f
                : g_SE[((size_t)bh * NP1 + ti) * Oo + col] + g_offE[(bh * SEGS + (ti >> 8)) * Oo + col];
            float pf = (ti == 0) ? 0.f
                : g_PF[((size_t)bh * NP1 + ti) * Oo + col] + g_offF[(bh * SEGS + ((ti - 1) >> 8)) * Oo + col];
            sum[rr] += (Eis[r] * se + Fis[r] * pf) * invl[r];
        }
    }

    float* outp = out + ((size_t)b * N1 + ib * 32) * Oo;
#pragma unroll
    for (int rr = 0; rr < 16; ++rr) {
        int r = rh + 2 * rr;
        outp[r * Oo + col] = 0.25f * sum[rr] + bias[col];
    }
}

// ---------------- launch ----------------
extern "C" void kernel_launch(void* const* d_in, const int* in_sizes, int n_in,
                              void* d_out, int out_size) {
    const float* x = (const float*)d_in[0];
    const float* prior = (const float*)d_in[1];
    const void* xmask = d_in[2];
    const float* Wlin = (const float*)d_in[3];
    const float* whead = (const float*)d_in[4];
    const float* asrc = (const float*)d_in[5];
    const float* adst = (const float*)d_in[6];
    const float* bias = (const float*)d_in[7];
    float* out = (float*)d_out;

    kdetect_mask<<<8, 256>>>((const unsigned*)xmask);
    k12_fused<<<dim3(64, Bb), 256>>>(x, prior, Wlin, whead, asrc, adst);
    k2c_meanhp<<<dim3(Hh, Bb), 128>>>(whead);
    ksortm<<<NBH, 1024>>>(xmask);
    kscan<<<dim3(SEGS, NBH), 256>>>();
    koff<<<NBH, 128>>>();
    kti<<<NBH, 1024>>>();
    kout<<<dim3(64, Bb), 256>>>(bias, out);
}